// round 6
// baseline (speedup 1.0000x reference)
#include <cuda_runtime.h>
#include <cstdint>

#define CH 256
#define NMAX 200000
#define KOFF 27
#define PATHS 4
#define NPK (KOFF * PATHS)
#define CW 384                         // conv output window rows
#define ACCS 65                        // Acc row stride (conflict-free)
#define MAXCK (KOFF * (CW / 32))       // worst-case chunks per block

// SMEM byte offsets for conv_all (dynamic shared)
#define OFF_ACC   0
#define OFF_GS    99840                // 384*65*4
#define OFF_WS    132608               // +4*32*64*4
#define OFF_OLOC  181760               // +3*64*64*4
#define OFF_CLO   182272               // +4*32*4
#define OFF_CMETA 183568               // +324*4
#define OFF_SLO   184864               // +324*4
#define CONV_SMEM 185088               // +2*27*4, rounded

// Scratch (device globals: no allocation allowed in kernel_launch)
__device__ float g_H[(size_t)NMAX * CH];     // lifted features, pre-rounded tf32
__device__ float g_A[(size_t)NMAX * CH];     // conv result (fp32)
__device__ float g_sum[CH];
__device__ float g_sumsq[CH];
__device__ float g_scale[CH];
__device__ float g_shift[CH];
__device__ float g_Wlr[65536];               // Wl permuted to [k][n], tf32-rounded
__device__ float g_W2r[65536];               // W2 [k][n], tf32-rounded
__device__ float g_Wcr[442368];              // Wc tf32-rounded

// ---------------------------------------------------------------------------
__device__ __forceinline__ float to_tf32(float f) {
    uint32_t u;
    asm("cvt.rna.tf32.f32 %0, %1;" : "=r"(u) : "f"(f));
    return __uint_as_float(u);
}

__device__ __forceinline__ void mma_tf32(float c[4], uint32_t a0, uint32_t a1,
                                         uint32_t a2, uint32_t a3,
                                         uint32_t b0, uint32_t b1) {
    asm volatile(
        "mma.sync.aligned.m16n8k8.row.col.f32.tf32.tf32.f32 "
        "{%0,%1,%2,%3}, {%4,%5,%6,%7}, {%8,%9}, {%0,%1,%2,%3};\n"
        : "+f"(c[0]), "+f"(c[1]), "+f"(c[2]), "+f"(c[3])
        : "r"(a0), "r"(a1), "r"(a2), "r"(a3), "r"(b0), "r"(b1));
}

__device__ __forceinline__ uint32_t smem_u32(const void* p) {
    return (uint32_t)__cvta_generic_to_shared(p);
}
__device__ __forceinline__ void cp16(uint32_t dst, const void* src, int sz) {
    asm volatile("cp.async.cg.shared.global [%0], [%1], 16, %2;"
                 :: "r"(dst), "l"(src), "r"(sz));
}
__device__ __forceinline__ void cp_commit() { asm volatile("cp.async.commit_group;"); }
template <int N> __device__ __forceinline__ void cp_wait() {
    asm volatile("cp.async.wait_group %0;" :: "n"(N));
}

// ---------------------------------------------------------------------------
__global__ void prep_weights(const float* __restrict__ Wl,
                             const float* __restrict__ W2,
                             const float* __restrict__ Wc) {
    int i = blockIdx.x * 256 + threadIdx.x;
    if (i < 65536) {
        int p = i >> 14, k = (i >> 6) & 255, d = i & 63;
        g_Wlr[k * 256 + p * 64 + d] = to_tf32(Wl[i]);
    } else if (i < 131072) {
        int j = i - 65536;
        g_W2r[j] = to_tf32(W2[j]);
    } else if (i < 131072 + 442368) {
        int j = i - 131072;
        g_Wcr[j] = to_tf32(Wc[j]);
    }
}

// ---------------------------------------------------------------------------
// H = tf32round(x @ Wl_cat + bl).  Tile 128x128, BK=16, 2-stage cp.async pipeline.
__global__ __launch_bounds__(256) void gemm_h(const float* __restrict__ x,
                                              const float* __restrict__ bl, int n) {
    __shared__ float As[2][128][20];
    __shared__ float Bs[2][16][136];
    const int colBase = blockIdx.x * 128;
    const int rowBase = blockIdx.y * 128;
    const int tid = threadIdx.x;
    const int warpId = tid >> 5, lane = tid & 31;
    const int grp = lane >> 2, qp = lane & 3;
    const int wm = (warpId & 3) * 32, wn = (warpId >> 2) * 64;

    float acc[2][8][4];
#pragma unroll
    for (int mt = 0; mt < 2; mt++)
#pragma unroll
        for (int nt = 0; nt < 8; nt++)
#pragma unroll
            for (int r = 0; r < 4; r++) acc[mt][nt][r] = 0.f;

    float4 ar[2];
    int arow[2], akq[2];
#pragma unroll
    for (int i = 0; i < 2; i++) { int ci = tid + i * 256; arow[i] = ci >> 2; akq[i] = ci & 3; }

#define LOAD_A(kt) do {                                                        \
    _Pragma("unroll")                                                          \
    for (int i = 0; i < 2; i++) {                                              \
        int gr = rowBase + arow[i];                                            \
        ar[i] = (gr < n) ? *(const float4*)&x[(size_t)gr * CH + (kt) * 16 + akq[i] * 4] \
                         : make_float4(0.f, 0.f, 0.f, 0.f);                    \
    } } while (0)
#define STS_A(b) do {                                                          \
    _Pragma("unroll")                                                          \
    for (int i = 0; i < 2; i++) {                                              \
        float4 v = ar[i];                                                      \
        v.x = to_tf32(v.x); v.y = to_tf32(v.y); v.z = to_tf32(v.z); v.w = to_tf32(v.w); \
        *(float4*)&As[b][arow[i]][akq[i] * 4] = v;                             \
    } } while (0)
#define LOAD_B(kt, b) do {                                                     \
    _Pragma("unroll")                                                          \
    for (int i = 0; i < 2; i++) {                                              \
        int ci = tid + i * 256; int kk = ci >> 5, nc = ci & 31;                \
        cp16(smem_u32(&Bs[b][kk][nc * 4]),                                     \
             &g_Wlr[(size_t)((kt) * 16 + kk) * 256 + colBase + nc * 4], 16);   \
    }                                                                          \
    cp_commit(); } while (0)
#define COMPUTE(b) do {                                                        \
    _Pragma("unroll")                                                          \
    for (int c8 = 0; c8 < 2; c8++) {                                           \
        int kk0 = c8 * 8;                                                      \
        uint32_t af[2][4], bf[8][2];                                           \
        _Pragma("unroll")                                                      \
        for (int mt = 0; mt < 2; mt++) {                                       \
            int r0 = wm + mt * 16 + grp;                                       \
            af[mt][0] = __float_as_uint(As[b][r0][kk0 + qp]);                  \
            af[mt][1] = __float_as_uint(As[b][r0 + 8][kk0 + qp]);              \
            af[mt][2] = __float_as_uint(As[b][r0][kk0 + qp + 4]);              \
            af[mt][3] = __float_as_uint(As[b][r0 + 8][kk0 + qp + 4]);          \
        }                                                                      \
        _Pragma("unroll")                                                      \
        for (int nt = 0; nt < 8; nt++) {                                       \
            int c0 = wn + nt * 8 + grp;                                        \
            bf[nt][0] = __float_as_uint(Bs[b][kk0 + qp][c0]);                  \
            bf[nt][1] = __float_as_uint(Bs[b][kk0 + qp + 4][c0]);              \
        }                                                                      \
        _Pragma("unroll")                                                      \
        for (int mt = 0; mt < 2; mt++)                                         \
            _Pragma("unroll")                                                  \
            for (int nt = 0; nt < 8; nt++)                                     \
                mma_tf32(acc[mt][nt], af[mt][0], af[mt][1], af[mt][2], af[mt][3], \
                         bf[nt][0], bf[nt][1]);                                \
    } } while (0)

    LOAD_B(0, 0);
    LOAD_B(1, 1);
    LOAD_A(0); STS_A(0); LOAD_A(1);
    cp_wait<1>(); __syncthreads();
    for (int kt = 0; kt < 16; kt++) {
        int b = kt & 1;
        if (kt + 1 < 16) STS_A(b ^ 1);
        if (kt + 2 < 16) LOAD_A(kt + 2);
        COMPUTE(b);
        if (kt + 1 < 16) cp_wait<0>();
        __syncthreads();
        if (kt + 2 < 16) LOAD_B(kt + 2, b);
    }
#undef LOAD_A
#undef STS_A
#undef LOAD_B
#undef COMPUTE

#pragma unroll
    for (int mt = 0; mt < 2; mt++) {
#pragma unroll
        for (int nt = 0; nt < 8; nt++) {
            int col = colBase + wn + nt * 8 + qp * 2;
            float b0 = bl[col], b1 = bl[col + 1];
            int gr0 = rowBase + wm + mt * 16 + grp;
            if (gr0 < n) {
                float2 o = make_float2(to_tf32(acc[mt][nt][0] + b0),
                                       to_tf32(acc[mt][nt][1] + b1));
                *(float2*)&g_H[(size_t)gr0 * CH + col] = o;
            }
            int gr1 = gr0 + 8;
            if (gr1 < n) {
                float2 o = make_float2(to_tf32(acc[mt][nt][2] + b0),
                                       to_tf32(acc[mt][nt][3] + b1));
                *(float2*)&g_H[(size_t)gr1 * CH + col] = o;
            }
        }
    }
}

// ---------------------------------------------------------------------------
// Output-stationary sparse conv over ALL 27 offsets, one (384-row window, path)
// per block.  out_idx is sorted per (p,k) -> binary search the window's pair
// range; gather H rows in 32-pair chunks (cp.async ring-4, depth-3 pipeline);
// tf32 mma; scatter-add into an SMEM accumulator (no global atomics).
// Epilogue stores g_A (plain, coalesced) and fuses BN sum/sumsq partials.
__global__ __launch_bounds__(256) void conv_all(const int* __restrict__ in_idx,
                                                const int* __restrict__ out_idx,
                                                int n, int M) {
    extern __shared__ char smem[];
    float* Acc  = (float*)(smem + OFF_ACC);    // [384][65]
    float* Gs   = (float*)(smem + OFF_GS);     // [4][32][64] swizzled
    float* Wsb  = (float*)(smem + OFF_WS);     // [3][64][64] swizzled
    int*   Oloc = (int*)(smem + OFF_OLOC);     // [4][32] local out rows
    int*   clo  = (int*)(smem + OFF_CLO);      // [MAXCK]
    int*   cme  = (int*)(smem + OFF_CMETA);    // [MAXCK] k|len<<5|ws<<11|wl<<13
    int*   sLo  = (int*)(smem + OFF_SLO);      // [27] + [27]
    int*   sHi  = sLo + KOFF;
    __shared__ int s_nc;

    const int p  = blockIdx.y;
    const int r0 = blockIdx.x * CW;
    const int tid = threadIdx.x;
    const size_t pbase = (size_t)p * KOFF * M;

    for (int i = tid; i < CW * ACCS; i += 256) Acc[i] = 0.f;

    if (tid < 2 * KOFF) {                      // window bounds per offset k
        int kk = tid >> 1;
        int hiB = r0 + CW; if (hiB > n) hiB = n;
        int v = (tid & 1) ? hiB : r0;
        const int* a = out_idx + pbase + (size_t)kk * M;
        int lo = 0, hi = M;
        while (lo < hi) { int mid = (lo + hi) >> 1;
                          if (__ldg(&a[mid]) < v) lo = mid + 1; else hi = mid; }
        if (tid & 1) sHi[kk] = lo; else sLo[kk] = lo;
    }
    __syncthreads();
    if (tid == 0) {                            // build chunk list
        int nc = 0, dk = 0;
        for (int k = 0; k < KOFF; k++) {
            int lo = sLo[k], m = sHi[k] - lo;
            if (m <= 0) continue;
            int ws = dk % 3;
            for (int c = 0; c < m; c += 32) {
                int len = m - c; if (len > 32) len = 32;
                clo[nc] = lo + c;
                cme[nc] = k | (len << 5) | (ws << 11) | ((c == 0) ? (1 << 13) : 0);
                nc++;
            }
            dk++;
        }
        s_nc = nc;
    }
    __syncthreads();
    const int nc = s_nc;

    const int warpId = tid >> 5, lane = tid & 31;
    const int grp = lane >> 2, qp = lane & 3;
    const int wm = (warpId & 1) * 16;          // 2 row-tiles of 16
    const int wn = (warpId >> 1) * 16;         // 4 col-tiles of 16
    const int pair = tid >> 3, seg = tid & 7;  // gather mapping

#define ISSUE(j) do {                                                          \
    int meta_ = cme[j]; int s_ = (j) & 3;                                      \
    int k_ = meta_ & 31; int len_ = (meta_ >> 5) & 63;                         \
    if (meta_ & (1 << 13)) {                                                   \
        int ws_ = (meta_ >> 11) & 3;                                           \
        const float* Wpk_ = g_Wcr + ((size_t)p * KOFF + k_) * 4096;            \
        float* wd_ = Wsb + ws_ * 4096;                                         \
        _Pragma("unroll")                                                      \
        for (int i2 = 0; i2 < 4; i2++) {                                       \
            int ci = tid + i2 * 256; int c_ = ci >> 4, q_ = ci & 15;           \
            cp16(smem_u32(&wd_[c_ * 64 + ((q_ * 4) ^ ((c_ & 3) << 3))]),       \
                 &Wpk_[c_ * 64 + q_ * 4], 16);                                 \
        }                                                                      \
    }                                                                          \
    size_t kb_ = pbase + (size_t)k_ * M + clo[j];                              \
    int jm_ = (pair < len_) ? __ldg(&in_idx[kb_ + pair]) : 0;                  \
    int sz_ = (pair < len_) ? 16 : 0;                                          \
    const float* hp_ = &g_H[(size_t)jm_ * CH + p * 64 + seg * 8];              \
    float* gd_ = Gs + s_ * 2048;                                               \
    int sw_ = (pair & 7) << 2;                                                 \
    cp16(smem_u32(&gd_[pair * 64 + ((seg * 8) ^ sw_)]), hp_, sz_);             \
    cp16(smem_u32(&gd_[pair * 64 + ((seg * 8 + 4) ^ sw_)]), hp_ + 4, sz_);     \
    if (seg == 0)                                                              \
        Oloc[s_ * 32 + pair] =                                                 \
            (pair < len_) ? (__ldg(&out_idx[kb_ + pair]) - r0) : -1;           \
    cp_commit(); } while (0)

    int issued = 0;
    int pre = nc < 3 ? nc : 3;
    for (; issued < pre; issued++) ISSUE(issued);

    for (int i = 0; i < nc; i++) {
        int pend = issued - i;
        if (pend >= 3) cp_wait<2>();
        else if (pend == 2) cp_wait<1>();
        else cp_wait<0>();
        __syncthreads();

        {   // compute chunk i: 32 pairs x 64 cols
            int s = i & 3;
            int ws = (cme[i] >> 11) & 3;
            const float* G = Gs + s * 2048;
            const float* Wk = Wsb + ws * 4096;
            float acc[2][4];
#pragma unroll
            for (int nt = 0; nt < 2; nt++)
#pragma unroll
                for (int r = 0; r < 4; r++) acc[nt][r] = 0.f;
            const int ra = wm + grp;
            const int sxa = grp << 2;
#pragma unroll
            for (int c8 = 0; c8 < 8; c8++) {
                int kk0 = c8 * 8;
                uint32_t a0 = __float_as_uint(G[ra * 64 + ((kk0 + qp) ^ sxa)]);
                uint32_t a1 = __float_as_uint(G[(ra + 8) * 64 + ((kk0 + qp) ^ sxa)]);
                uint32_t a2 = __float_as_uint(G[ra * 64 + ((kk0 + qp + 4) ^ sxa)]);
                uint32_t a3 = __float_as_uint(G[(ra + 8) * 64 + ((kk0 + qp + 4) ^ sxa)]);
#pragma unroll
                for (int nt = 0; nt < 2; nt++) {
                    int c0 = wn + nt * 8 + grp;
                    uint32_t b0 = __float_as_uint(Wk[(kk0 + qp) * 64 + (c0 ^ (qp << 3))]);
                    uint32_t b1 = __float_as_uint(Wk[(kk0 + qp + 4) * 64 + (c0 ^ (qp << 3))]);
                    mma_tf32(acc[nt], a0, a1, a2, a3, b0, b1);
                }
            }
            int lr0 = Oloc[s * 32 + ra];
            int lr1 = Oloc[s * 32 + ra + 8];
#pragma unroll
            for (int nt = 0; nt < 2; nt++) {
                int col = wn + nt * 8 + qp * 2;
                if (lr0 >= 0) {
                    Acc[lr0 * ACCS + col]     += acc[nt][0];
                    Acc[lr0 * ACCS + col + 1] += acc[nt][1];
                }
                if (lr1 >= 0) {
                    Acc[lr1 * ACCS + col]     += acc[nt][2];
                    Acc[lr1 * ACCS + col + 1] += acc[nt][3];
                }
            }
        }
        __syncthreads();
        if (issued < nc) { ISSUE(issued); issued++; }
    }
#undef ISSUE

    // Epilogue: store window to g_A + BN partials (rows >= n are zero)
    __syncthreads();
    float s1 = 0.f, s2 = 0.f;
    int col = tid & 63, rg = tid >> 6;
    for (int rr = rg; rr < CW; rr += 4) {
        float v = Acc[rr * ACCS + col];
        int gr = r0 + rr;
        if (gr < n) g_A[(size_t)gr * CH + p * 64 + col] = v;
        s1 += v; s2 += v * v;
    }
    float* red = Gs;                            // reuse gather buffer
    red[rg * 64 + col] = s1;
    red[256 + rg * 64 + col] = s2;
    __syncthreads();
    if (rg == 0) {
#pragma unroll
        for (int i = 1; i < 4; i++) {
            s1 += red[i * 64 + col];
            s2 += red[256 + i * 64 + col];
        }
        atomicAdd(&g_sum[p * 64 + col], s1);
        atomicAdd(&g_sumsq[p * 64 + col], s2);
    }
}

// ---------------------------------------------------------------------------
__global__ void bn_finalize(const float* __restrict__ gamma,
                            const float* __restrict__ beta, int n) {
    int j = threadIdx.x;
    float inv = 1.f / (float)n;
    float mu = g_sum[j] * inv;
    float var = g_sumsq[j] * inv - mu * mu;
    float sc = gamma[j] * rsqrtf(var + 1e-5f);
    g_scale[j] = sc;
    g_shift[j] = beta[j] - mu * sc;
}

// ---------------------------------------------------------------------------
// out = relu(bn(A)) @ W2 + b2 + x.  Same pipelined skeleton as gemm_h.
__global__ __launch_bounds__(256) void gemm_out(const float* __restrict__ b2,
                                                const float* __restrict__ x,
                                                float* __restrict__ out, int n) {
    __shared__ float As[2][128][20];
    __shared__ float Bs[2][16][136];
    __shared__ float sc[256], sh[256];
    const int colBase = blockIdx.x * 128;
    const int rowBase = blockIdx.y * 128;
    const int tid = threadIdx.x;
    const int warpId = tid >> 5, lane = tid & 31;
    const int grp = lane >> 2, qp = lane & 3;
    const int wm = (warpId & 3) * 32, wn = (warpId >> 2) * 64;

    sc[tid] = g_scale[tid];
    sh[tid] = g_shift[tid];

    float acc[2][8][4];
#pragma unroll
    for (int mt = 0; mt < 2; mt++)
#pragma unroll
        for (int nt = 0; nt < 8; nt++)
#pragma unroll
            for (int r = 0; r < 4; r++) acc[mt][nt][r] = 0.f;

    float4 ar[2];
    int arow[2], akq[2];
#pragma unroll
    for (int i = 0; i < 2; i++) { int ci = tid + i * 256; arow[i] = ci >> 2; akq[i] = ci & 3; }

#define LOAD_A(kt) do {                                                        \
    _Pragma("unroll")                                                          \
    for (int i = 0; i < 2; i++) {                                              \
        int gr = rowBase + arow[i];                                            \
        ar[i] = (gr < n) ? *(const float4*)&g_A[(size_t)gr * CH + (kt) * 16 + akq[i] * 4] \
                         : make_float4(0.f, 0.f, 0.f, 0.f);                    \
    } } while (0)
#define STS_A(b, kt) do {                                                      \
    _Pragma("unroll")                                                          \
    for (int i = 0; i < 2; i++) {                                              \
        float4 v = ar[i];                                                      \
        int c0 = (kt) * 16 + akq[i] * 4;                                       \
        v.x = to_tf32(fmaxf(v.x * sc[c0 + 0] + sh[c0 + 0], 0.f));              \
        v.y = to_tf32(fmaxf(v.y * sc[c0 + 1] + sh[c0 + 1], 0.f));              \
        v.z = to_tf32(fmaxf(v.z * sc[c0 + 2] + sh[c0 + 2], 0.f));              \
        v.w = to_tf32(fmaxf(v.w * sc[c0 + 3] + sh[c0 + 3], 0.f));              \
        *(float4*)&As[b][arow[i]][akq[i] * 4] = v;                             \
    } } while (0)
#define LOAD_B(kt, b) do {                                                     \
    _Pragma("unroll")                                                          \
    for (int i = 0; i < 2; i++) {                                              \
        int ci = tid + i * 256; int kk = ci >> 5, nc = ci & 31;                \
        cp16(smem_u32(&Bs[b][kk][nc * 4]),                                     \
             &g_W2r[(size_t)((kt) * 16 + kk) * 256 + colBase + nc * 4], 16);   \
    }                                                                          \
    cp_commit(); } while (0)
#define COMPUTE(b) do {                                                        \
    _Pragma("unroll")                                                          \
    for (int c8 = 0; c8 < 2; c8++) {                                           \
        int kk0 = c8 * 8;                                                      \
        uint32_t af[2][4], bf[8][2];                                           \
        _Pragma("unroll")                                                      \
        for (int mt = 0; mt < 2; mt++) {                                       \
            int r0 = wm + mt * 16 + grp;                                       \
            af[mt][0] = __float_as_uint(As[b][r0][kk0 + qp]);                  \
            af[mt][1] = __float_as_uint(As[b][r0 + 8][kk0 + qp]);              \
            af[mt][2] = __float_as_uint(As[b][r0][kk0 + qp + 4]);              \
            af[mt][3] = __float_as_uint(As[b][r0 + 8][kk0 + qp + 4]);          \
        }                                                                      \
        _Pragma("unroll")                                                      \
        for (int nt = 0; nt < 8; nt++) {                                       \
            int c0 = wn + nt * 8 + grp;                                        \
            bf[nt][0] = __float_as_uint(Bs[b][kk0 + qp][c0]);                  \
            bf[nt][1] = __float_as_uint(Bs[b][kk0 + qp + 4][c0]);              \
        }                                                                      \
        _Pragma("unroll")                                                      \
        for (int mt = 0; mt < 2; mt++)                                         \
            _Pragma("unroll")                                                  \
            for (int nt = 0; nt < 8; nt++)                                     \
                mma_tf32(acc[mt][nt], af[mt][0], af[mt][1], af[mt][2], af[mt][3], \
                         bf[nt][0], bf[nt][1]);                                \
    } } while (0)

    LOAD_B(0, 0);
    LOAD_B(1, 1);
    LOAD_A(0);
    __syncthreads();                 // publish sc/sh before STS_A uses them
    STS_A(0, 0); LOAD_A(1);
    cp_wait<1>(); __syncthreads();
    for (int kt = 0; kt < 16; kt++) {
        int b = kt & 1;
        if (kt + 1 < 16) STS_A(b ^ 1, kt + 1);
        if (kt + 2 < 16) LOAD_A(kt + 2);
        COMPUTE(b);
        if (kt + 1 < 16) cp_wait<0>();
        __syncthreads();
        if (kt + 2 < 16) LOAD_B(kt + 2, b);
    }
#undef LOAD_A
#undef STS_A
#undef LOAD_B
#undef COMPUTE

#pragma unroll
    for (int mt = 0; mt < 2; mt++) {
#pragma unroll
        for (int nt = 0; nt < 8; nt++) {
            int col = colBase + wn + nt * 8 + qp * 2;
            float b0 = b2[col], b1 = b2[col + 1];
            int gr0 = rowBase + wm + mt * 16 + grp;
            if (gr0 < n) {
                float2 xr = *(const float2*)&x[(size_t)gr0 * CH + col];
                *(float2*)&out[(size_t)gr0 * CH + col] =
                    make_float2(acc[mt][nt][0] + b0 + xr.x, acc[mt][nt][1] + b1 + xr.y);
            }
            int gr1 = gr0 + 8;
            if (gr1 < n) {
                float2 xr = *(const float2*)&x[(size_t)gr1 * CH + col];
                *(float2*)&out[(size_t)gr1 * CH + col] =
                    make_float2(acc[mt][nt][2] + b0 + xr.x, acc[mt][nt][3] + b1 + xr.y);
            }
        }
    }
}

// ---------------------------------------------------------------------------
extern "C" void kernel_launch(void* const* d_in, const int* in_sizes, int n_in,
                              void* d_out, int out_size) {
    const float* x     = (const float*)d_in[0];
    const float* Wl    = (const float*)d_in[1];
    const float* bl    = (const float*)d_in[2];
    const float* Wc    = (const float*)d_in[3];
    const float* gamma = (const float*)d_in[4];
    const float* beta  = (const float*)d_in[5];
    const float* W2    = (const float*)d_in[6];
    const float* b2    = (const float*)d_in[7];
    const int* in_idx  = (const int*)d_in[8];
    const int* out_idx = (const int*)d_in[9];
    float* out = (float*)d_out;

    int n = in_sizes[0] / CH;                 // 200000
    int M = in_sizes[8] / NPK;                // max pairs per (p,k)

    cudaFuncSetAttribute(conv_all, cudaFuncAttributeMaxDynamicSharedMemorySize,
                         CONV_SMEM);

    void* pS = nullptr; void* pQ = nullptr;
    cudaGetSymbolAddress(&pS, g_sum);
    cudaGetSymbolAddress(&pQ, g_sumsq);
    cudaMemsetAsync(pS, 0, CH * sizeof(float));
    cudaMemsetAsync(pQ, 0, CH * sizeof(float));

    prep_weights<<<2240, 256>>>(Wl, W2, Wc);
    gemm_h<<<dim3(2, (n + 127) / 128), 256>>>(x, bl, n);
    conv_all<<<dim3((n + CW - 1) / CW, PATHS), 256, CONV_SMEM>>>(in_idx, out_idx, n, M);
    bn_finalize<<<1, 256>>>(gamma, beta, n);
    gemm_out<<<dim3(2, (n + 127) / 128), 256>>>(b2, x, out, n);
}

// round 7
// speedup vs baseline: 1.7388x; 1.7388x over previous
#include <cuda_runtime.h>
#include <cstdint>

#define CH 256
#define NMAX 200000
#define KOFF 27
#define PATHS 4
#define NPK (KOFF * PATHS)

// Scratch (device globals: no allocation allowed in kernel_launch)
__device__ float g_H[(size_t)NMAX * CH];     // lifted features, pre-rounded tf32
__device__ float g_A[(size_t)NMAX * CH];     // conv result (fp32)
__device__ float g_sum[CH];
__device__ float g_sumsq[CH];
__device__ float g_scale[CH];
__device__ float g_shift[CH];
__device__ float g_Wlr[65536];               // Wl permuted to [k][n], tf32-rounded
__device__ float g_W2r[65536];               // W2 [k][n], tf32-rounded
__device__ float g_Wcr[442368];              // Wc tf32-rounded
__device__ int   g_cnt[NPK];                 // valid pair count per (p,k)

// ---------------------------------------------------------------------------
__device__ __forceinline__ float to_tf32(float f) {
    uint32_t u;
    asm("cvt.rna.tf32.f32 %0, %1;" : "=r"(u) : "f"(f));
    return __uint_as_float(u);
}

__device__ __forceinline__ void mma_tf32(float c[4], uint32_t a0, uint32_t a1,
                                         uint32_t a2, uint32_t a3,
                                         uint32_t b0, uint32_t b1) {
    asm volatile(
        "mma.sync.aligned.m16n8k8.row.col.f32.tf32.tf32.f32 "
        "{%0,%1,%2,%3}, {%4,%5,%6,%7}, {%8,%9}, {%0,%1,%2,%3};\n"
        : "+f"(c[0]), "+f"(c[1]), "+f"(c[2]), "+f"(c[3])
        : "r"(a0), "r"(a1), "r"(a2), "r"(a3), "r"(b0), "r"(b1));
}

__device__ __forceinline__ uint32_t smem_u32(const void* p) {
    return (uint32_t)__cvta_generic_to_shared(p);
}
__device__ __forceinline__ void cp16(uint32_t dst, const void* src, int sz) {
    asm volatile("cp.async.cg.shared.global [%0], [%1], 16, %2;"
                 :: "r"(dst), "l"(src), "r"(sz));
}
__device__ __forceinline__ void cp_commit() { asm volatile("cp.async.commit_group;"); }
template <int N> __device__ __forceinline__ void cp_wait() {
    asm volatile("cp.async.wait_group %0;" :: "n"(N));
}
__device__ __forceinline__ void red_v4(float* dst, float4 v) {
    asm volatile("red.global.add.v4.f32 [%0], {%1,%2,%3,%4};"
                 :: "l"(dst), "f"(v.x), "f"(v.y), "f"(v.z), "f"(v.w) : "memory");
}

// ---------------------------------------------------------------------------
__global__ void prep_weights(const float* __restrict__ Wl,
                             const float* __restrict__ W2,
                             const float* __restrict__ Wc) {
    int i = blockIdx.x * 256 + threadIdx.x;
    if (i < 65536) {
        int p = i >> 14, k = (i >> 6) & 255, d = i & 63;
        g_Wlr[k * 256 + p * 64 + d] = to_tf32(Wl[i]);
    } else if (i < 131072) {
        int j = i - 65536;
        g_W2r[j] = to_tf32(W2[j]);
    } else if (i < 131072 + 442368) {
        int j = i - 131072;
        g_Wcr[j] = to_tf32(Wc[j]);
    }
}

// Valid pairs per (p,k) are a prefix -> binary search the boundary.
__global__ void count_pairs(const int* __restrict__ in_idx, int n, int M) {
    int pk = threadIdx.x;
    if (pk >= NPK) return;
    const int* a = in_idx + (size_t)pk * M;
    int lo = 0, hi = M;
    while (lo < hi) {
        int mid = (lo + hi) >> 1;
        if (__ldg(&a[mid]) < n) lo = mid + 1; else hi = mid;
    }
    g_cnt[pk] = lo;
}

// ---------------------------------------------------------------------------
// H = tf32round(x @ Wl_cat + bl).  128-row tile; loops over both 128-col
// halves so x is read from DRAM once (2nd pass hits L2).  BK=16, 2-stage
// cp.async pipeline.
__global__ __launch_bounds__(256) void gemm_h(const float* __restrict__ x,
                                              const float* __restrict__ bl, int n) {
    __shared__ float As[2][128][20];
    __shared__ float Bs[2][16][136];
    const int rowBase = blockIdx.x * 128;
    const int tid = threadIdx.x;
    const int warpId = tid >> 5, lane = tid & 31;
    const int grp = lane >> 2, qp = lane & 3;
    const int wm = (warpId & 3) * 32, wn = (warpId >> 2) * 64;

    float4 ar[2];
    int arow[2], akq[2];
#pragma unroll
    for (int i = 0; i < 2; i++) { int ci = tid + i * 256; arow[i] = ci >> 2; akq[i] = ci & 3; }

#define LOAD_A(kt) do {                                                        \
    _Pragma("unroll")                                                          \
    for (int i = 0; i < 2; i++) {                                              \
        int gr = rowBase + arow[i];                                            \
        ar[i] = (gr < n) ? *(const float4*)&x[(size_t)gr * CH + (kt) * 16 + akq[i] * 4] \
                         : make_float4(0.f, 0.f, 0.f, 0.f);                    \
    } } while (0)
#define STS_A(b) do {                                                          \
    _Pragma("unroll")                                                          \
    for (int i = 0; i < 2; i++) {                                              \
        float4 v = ar[i];                                                      \
        v.x = to_tf32(v.x); v.y = to_tf32(v.y); v.z = to_tf32(v.z); v.w = to_tf32(v.w); \
        *(float4*)&As[b][arow[i]][akq[i] * 4] = v;                             \
    } } while (0)
#define LOAD_B(kt, b) do {                                                     \
    _Pragma("unroll")                                                          \
    for (int i = 0; i < 2; i++) {                                              \
        int ci = tid + i * 256; int kk = ci >> 5, nc = ci & 31;                \
        cp16(smem_u32(&Bs[b][kk][nc * 4]),                                     \
             &g_Wlr[(size_t)((kt) * 16 + kk) * 256 + colBase + nc * 4], 16);   \
    }                                                                          \
    cp_commit(); } while (0)
#define COMPUTE(b) do {                                                        \
    _Pragma("unroll")                                                          \
    for (int c8 = 0; c8 < 2; c8++) {                                           \
        int kk0 = c8 * 8;                                                      \
        uint32_t af[2][4], bf[8][2];                                           \
        _Pragma("unroll")                                                      \
        for (int mt = 0; mt < 2; mt++) {                                       \
            int r0 = wm + mt * 16 + grp;                                       \
            af[mt][0] = __float_as_uint(As[b][r0][kk0 + qp]);                  \
            af[mt][1] = __float_as_uint(As[b][r0 + 8][kk0 + qp]);              \
            af[mt][2] = __float_as_uint(As[b][r0][kk0 + qp + 4]);              \
            af[mt][3] = __float_as_uint(As[b][r0 + 8][kk0 + qp + 4]);          \
        }                                                                      \
        _Pragma("unroll")                                                      \
        for (int nt = 0; nt < 8; nt++) {                                       \
            int c0 = wn + nt * 8 + grp;                                        \
            bf[nt][0] = __float_as_uint(Bs[b][kk0 + qp][c0]);                  \
            bf[nt][1] = __float_as_uint(Bs[b][kk0 + qp + 4][c0]);              \
        }                                                                      \
        _Pragma("unroll")                                                      \
        for (int mt = 0; mt < 2; mt++)                                         \
            _Pragma("unroll")                                                  \
            for (int nt = 0; nt < 8; nt++)                                     \
                mma_tf32(acc[mt][nt], af[mt][0], af[mt][1], af[mt][2], af[mt][3], \
                         bf[nt][0], bf[nt][1]);                                \
    } } while (0)

    for (int cb = 0; cb < 2; cb++) {
        const int colBase = cb * 128;
        float acc[2][8][4];
#pragma unroll
        for (int mt = 0; mt < 2; mt++)
#pragma unroll
            for (int nt = 0; nt < 8; nt++)
#pragma unroll
                for (int r = 0; r < 4; r++) acc[mt][nt][r] = 0.f;

        LOAD_B(0, 0);
        LOAD_B(1, 1);
        LOAD_A(0); STS_A(0); LOAD_A(1);
        cp_wait<1>(); __syncthreads();
        for (int kt = 0; kt < 16; kt++) {
            int b = kt & 1;
            if (kt + 1 < 16) STS_A(b ^ 1);
            if (kt + 2 < 16) LOAD_A(kt + 2);
            COMPUTE(b);
            if (kt + 1 < 16) cp_wait<0>();
            __syncthreads();
            if (kt + 2 < 16) LOAD_B(kt + 2, b);
        }

#pragma unroll
        for (int mt = 0; mt < 2; mt++) {
#pragma unroll
            for (int nt = 0; nt < 8; nt++) {
                int col = colBase + wn + nt * 8 + qp * 2;
                float b0 = bl[col], b1 = bl[col + 1];
                int gr0 = rowBase + wm + mt * 16 + grp;
                if (gr0 < n) {
                    float2 o = make_float2(to_tf32(acc[mt][nt][0] + b0),
                                           to_tf32(acc[mt][nt][1] + b1));
                    *(float2*)&g_H[(size_t)gr0 * CH + col] = o;
                }
                int gr1 = gr0 + 8;
                if (gr1 < n) {
                    float2 o = make_float2(to_tf32(acc[mt][nt][2] + b0),
                                           to_tf32(acc[mt][nt][3] + b1));
                    *(float2*)&g_H[(size_t)gr1 * CH + col] = o;
                }
            }
        }
        __syncthreads();            // protect As/Bs before next col-half
    }
#undef LOAD_A
#undef STS_A
#undef LOAD_B
#undef COMPUTE
}

// ---------------------------------------------------------------------------
// Center offset (k=13): in_idx == out_idx == identity, covers ALL rows.
// Dense GEMM g_A[:, p*64..] = H[:, p*64..] @ Wc[p][13]; plain stores, and it
// initializes g_A (no memset needed).
__global__ __launch_bounds__(256) void conv_center(int n) {
    __shared__ float Gs[128][64];   // swizzled: (m,c) at col c ^ ((m&7)<<2)
    __shared__ float Ws[64][64];    // swizzled: (k,c) at col c ^ ((k&3)<<3)
    const int p = blockIdx.y;
    const int r0 = blockIdx.x * 128;
    const int tid = threadIdx.x;

    const float* Wpk = g_Wcr + (size_t)(p * KOFF + 13) * 4096;
#pragma unroll
    for (int i = 0; i < 4; i++) {
        int ci = tid + i * 256;
        int c = ci >> 4, q = ci & 15;
        cp16(smem_u32(&Ws[c][(q * 4) ^ ((c & 3) << 3)]), &Wpk[c * 64 + q * 4], 16);
    }
    {
        int m = tid >> 1, half = tid & 1;
        int gr = r0 + m;
        int sz = (gr < n) ? 16 : 0;
        const float* hp = &g_H[(size_t)(gr < n ? gr : 0) * CH + p * 64 + half * 32];
#pragma unroll
        for (int q = 0; q < 8; q++) {
            int cb = half * 32 + q * 4;
            cp16(smem_u32(&Gs[m][cb ^ ((m & 7) << 2)]), hp + q * 4, sz);
        }
    }
    cp_commit(); cp_wait<0>(); __syncthreads();

    const int warpId = tid >> 5, lane = tid & 31;
    const int grp = lane >> 2, qp = lane & 3;
    const int wm = (warpId & 3) * 32, wn = (warpId >> 2) * 32;
    const int sx = grp << 2, wsx = qp << 3;

    float acc[2][4][4];
#pragma unroll
    for (int mt = 0; mt < 2; mt++)
#pragma unroll
        for (int nt = 0; nt < 4; nt++)
#pragma unroll
            for (int r = 0; r < 4; r++) acc[mt][nt][r] = 0.f;

#pragma unroll
    for (int c8 = 0; c8 < 8; c8++) {
        int kk0 = c8 * 8;
        uint32_t af[2][4], bf[4][2];
#pragma unroll
        for (int mt = 0; mt < 2; mt++) {
            int r0w = wm + mt * 16 + grp;
            af[mt][0] = __float_as_uint(Gs[r0w][(kk0 + qp) ^ sx]);
            af[mt][1] = __float_as_uint(Gs[r0w + 8][(kk0 + qp) ^ sx]);
            af[mt][2] = __float_as_uint(Gs[r0w][(kk0 + qp + 4) ^ sx]);
            af[mt][3] = __float_as_uint(Gs[r0w + 8][(kk0 + qp + 4) ^ sx]);
        }
#pragma unroll
        for (int nt = 0; nt < 4; nt++) {
            int c0 = wn + nt * 8 + grp;
            bf[nt][0] = __float_as_uint(Ws[kk0 + qp][c0 ^ wsx]);
            bf[nt][1] = __float_as_uint(Ws[kk0 + qp + 4][c0 ^ wsx]);
        }
#pragma unroll
        for (int mt = 0; mt < 2; mt++)
#pragma unroll
            for (int nt = 0; nt < 4; nt++)
                mma_tf32(acc[mt][nt], af[mt][0], af[mt][1], af[mt][2], af[mt][3],
                         bf[nt][0], bf[nt][1]);
    }
    __syncthreads();

#pragma unroll
    for (int mt = 0; mt < 2; mt++)
#pragma unroll
        for (int nt = 0; nt < 4; nt++) {
            int col = wn + nt * 8 + qp * 2;
            int rw = wm + mt * 16 + grp;
            *(float2*)&Gs[rw][col ^ ((rw & 7) << 2)] =
                make_float2(acc[mt][nt][0], acc[mt][nt][1]);
            *(float2*)&Gs[rw + 8][col ^ ((rw & 7) << 2)] =
                make_float2(acc[mt][nt][2], acc[mt][nt][3]);
        }
    __syncthreads();

#pragma unroll
    for (int i = 0; i < 8; i++) {
        int idx = tid + i * 256;
        int row = idx >> 4, c4 = idx & 15;
        int gr = r0 + row;
        if (gr < n) {
            float4 v = *(const float4*)&Gs[row][(c4 * 4) ^ ((row & 7) << 2)];
            *(float4*)&g_A[(size_t)gr * CH + p * 64 + c4 * 4] = v;
        }
    }
}

// ---------------------------------------------------------------------------
// Sparse conv over the 26 non-center offsets: 128-pair tile per block,
// cp.async gather (XOR-swizzled), tf32 mma, SMEM-staged v4-RED scatter.
__global__ __launch_bounds__(256) void conv_scatter(const int* __restrict__ in_idx,
                                                    const int* __restrict__ out_idx,
                                                    int M) {
    __shared__ float Gs[128][64];   // swizzled: (m,c) at col c ^ ((m&7)<<2)
    __shared__ float Ws[64][64];    // swizzled: (k,c) at col c ^ ((k&3)<<3)
    __shared__ int Os[128];
    const int p = blockIdx.z;
    const int ky = blockIdx.y;
    const int k = ky + (ky >= 13);  // skip center
    const int pk = p * KOFF + k;
    const int cnt = g_cnt[pk];
    const int base0 = blockIdx.x * 128;
    if (base0 >= cnt) return;
    int rem = cnt - base0; if (rem > 128) rem = 128;
    const size_t base = (size_t)pk * M + base0;
    const int tid = threadIdx.x;

    const float* Wpk = g_Wcr + (size_t)pk * 4096;
#pragma unroll
    for (int i = 0; i < 4; i++) {
        int ci = tid + i * 256;
        int c = ci >> 4, q = ci & 15;
        cp16(smem_u32(&Ws[c][(q * 4) ^ ((c & 3) << 3)]), &Wpk[c * 64 + q * 4], 16);
    }
    {
        int m = tid >> 1, half = tid & 1;
        int jm = (m < rem) ? __ldg(&in_idx[base + m]) : 0;
        int sz = (m < rem) ? 16 : 0;
        const float* hp = &g_H[(size_t)jm * CH + p * 64 + half * 32];
#pragma unroll
        for (int q = 0; q < 8; q++) {
            int cb = half * 32 + q * 4;
            cp16(smem_u32(&Gs[m][cb ^ ((m & 7) << 2)]), hp + q * 4, sz);
        }
        if (half == 0)
            Os[m] = (m < rem) ? __ldg(&out_idx[base + m]) : -1;
    }
    cp_commit(); cp_wait<0>(); __syncthreads();

    const int warpId = tid >> 5, lane = tid & 31;
    const int grp = lane >> 2, qp = lane & 3;
    const int wm = (warpId & 3) * 32, wn = (warpId >> 2) * 32;
    const int sx = grp << 2, wsx = qp << 3;

    float acc[2][4][4];
#pragma unroll
    for (int mt = 0; mt < 2; mt++)
#pragma unroll
        for (int nt = 0; nt < 4; nt++)
#pragma unroll
            for (int r = 0; r < 4; r++) acc[mt][nt][r] = 0.f;

#pragma unroll
    for (int c8 = 0; c8 < 8; c8++) {
        int kk0 = c8 * 8;
        uint32_t af[2][4], bf[4][2];
#pragma unroll
        for (int mt = 0; mt < 2; mt++) {
            int r0 = wm + mt * 16 + grp;
            af[mt][0] = __float_as_uint(Gs[r0][(kk0 + qp) ^ sx]);
            af[mt][1] = __float_as_uint(Gs[r0 + 8][(kk0 + qp) ^ sx]);
            af[mt][2] = __float_as_uint(Gs[r0][(kk0 + qp + 4) ^ sx]);
            af[mt][3] = __float_as_uint(Gs[r0 + 8][(kk0 + qp + 4) ^ sx]);
        }
#pragma unroll
        for (int nt = 0; nt < 4; nt++) {
            int c0 = wn + nt * 8 + grp;
            bf[nt][0] = __float_as_uint(Ws[kk0 + qp][c0 ^ wsx]);
            bf[nt][1] = __float_as_uint(Ws[kk0 + qp + 4][c0 ^ wsx]);
        }
#pragma unroll
        for (int mt = 0; mt < 2; mt++)
#pragma unroll
            for (int nt = 0; nt < 4; nt++)
                mma_tf32(acc[mt][nt], af[mt][0], af[mt][1], af[mt][2], af[mt][3],
                         bf[nt][0], bf[nt][1]);
    }
    __syncthreads();

#pragma unroll
    for (int mt = 0; mt < 2; mt++)
#pragma unroll
        for (int nt = 0; nt < 4; nt++) {
            int col = wn + nt * 8 + qp * 2;
            int r0 = wm + mt * 16 + grp;
            *(float2*)&Gs[r0][col ^ ((r0 & 7) << 2)] =
                make_float2(acc[mt][nt][0], acc[mt][nt][1]);
            *(float2*)&Gs[r0 + 8][col ^ ((r0 & 7) << 2)] =
                make_float2(acc[mt][nt][2], acc[mt][nt][3]);
        }
    __syncthreads();

#pragma unroll
    for (int i = 0; i < 8; i++) {
        int idx = tid + i * 256;
        int row = idx >> 4, c4 = idx & 15;
        int o = Os[row];
        if (o >= 0) {
            float4 v = *(const float4*)&Gs[row][(c4 * 4) ^ ((row & 7) << 2)];
            red_v4(&g_A[(size_t)o * CH + p * 64 + c4 * 4], v);
        }
    }
}

// ---------------------------------------------------------------------------
__global__ __launch_bounds__(256) void bn_stats(int n) {
    __shared__ float4 rs[4][64], rq[4][64];
    int tid = threadIdx.x;
    int cq = tid & 63;
    int rl = tid >> 6;
    float4 s = make_float4(0.f, 0.f, 0.f, 0.f);
    float4 s2 = make_float4(0.f, 0.f, 0.f, 0.f);
#pragma unroll 8
    for (int r = blockIdx.x * 4 + rl; r < n; r += gridDim.x * 4) {
        float4 v = *(const float4*)&g_A[(size_t)r * CH + cq * 4];
        s.x += v.x; s.y += v.y; s.z += v.z; s.w += v.w;
        s2.x += v.x * v.x; s2.y += v.y * v.y; s2.z += v.z * v.z; s2.w += v.w * v.w;
    }
    rs[rl][cq] = s; rq[rl][cq] = s2;
    __syncthreads();
    if (rl == 0) {
#pragma unroll
        for (int i = 1; i < 4; i++) {
            float4 a = rs[i][cq], b = rq[i][cq];
            s.x += a.x; s.y += a.y; s.z += a.z; s.w += a.w;
            s2.x += b.x; s2.y += b.y; s2.z += b.z; s2.w += b.w;
        }
        int c = cq * 4;
        atomicAdd(&g_sum[c + 0], s.x);  atomicAdd(&g_sum[c + 1], s.y);
        atomicAdd(&g_sum[c + 2], s.z);  atomicAdd(&g_sum[c + 3], s.w);
        atomicAdd(&g_sumsq[c + 0], s2.x); atomicAdd(&g_sumsq[c + 1], s2.y);
        atomicAdd(&g_sumsq[c + 2], s2.z); atomicAdd(&g_sumsq[c + 3], s2.w);
    }
}

__global__ void bn_finalize(const float* __restrict__ gamma,
                            const float* __restrict__ beta, int n) {
    int j = threadIdx.x;
    float inv = 1.f / (float)n;
    float mu = g_sum[j] * inv;
    float var = g_sumsq[j] * inv - mu * mu;
    float sc = gamma[j] * rsqrtf(var + 1e-5f);
    g_scale[j] = sc;
    g_shift[j] = beta[j] - mu * sc;
}

// ---------------------------------------------------------------------------
// out = relu(bn(A)) @ W2 + b2 + x.  128-row tile; loops over both col halves
// so g_A is read from DRAM once.  bn+relu fused into A staging.
__global__ __launch_bounds__(256) void gemm_out(const float* __restrict__ b2,
                                                const float* __restrict__ x,
                                                float* __restrict__ out, int n) {
    __shared__ float As[2][128][20];
    __shared__ float Bs[2][16][136];
    __shared__ float sc[256], sh[256];
    const int rowBase = blockIdx.x * 128;
    const int tid = threadIdx.x;
    const int warpId = tid >> 5, lane = tid & 31;
    const int grp = lane >> 2, qp = lane & 3;
    const int wm = (warpId & 3) * 32, wn = (warpId >> 2) * 64;

    sc[tid] = g_scale[tid];
    sh[tid] = g_shift[tid];
    __syncthreads();                 // publish sc/sh

    float4 ar[2];
    int arow[2], akq[2];
#pragma unroll
    for (int i = 0; i < 2; i++) { int ci = tid + i * 256; arow[i] = ci >> 2; akq[i] = ci & 3; }

#define LOAD_A(kt) do {                                                        \
    _Pragma("unroll")                                                          \
    for (int i = 0; i < 2; i++) {                                              \
        int gr = rowBase + arow[i];                                            \
        ar[i] = (gr < n) ? *(const float4*)&g_A[(size_t)gr * CH + (kt) * 16 + akq[i] * 4] \
                         : make_float4(0.f, 0.f, 0.f, 0.f);                    \
    } } while (0)
#define STS_A(b, kt) do {                                                      \
    _Pragma("unroll")                                                          \
    for (int i = 0; i < 2; i++) {                                              \
        float4 v = ar[i];                                                      \
        int c0 = (kt) * 16 + akq[i] * 4;                                       \
        v.x = to_tf32(fmaxf(v.x * sc[c0 + 0] + sh[c0 + 0], 0.f));              \
        v.y = to_tf32(fmaxf(v.y * sc[c0 + 1] + sh[c0 + 1], 0.f));              \
        v.z = to_tf32(fmaxf(v.z * sc[c0 + 2] + sh[c0 + 2], 0.f));              \
        v.w = to_tf32(fmaxf(v.w * sc[c0 + 3] + sh[c0 + 3], 0.f));              \
        *(float4*)&As[b][arow[i]][akq[i] * 4] = v;                             \
    } } while (0)
#define LOAD_B(kt, b) do {                                                     \
    _Pragma("unroll")                                                          \
    for (int i = 0; i < 2; i++) {                                              \
        int ci = tid + i * 256; int kk = ci >> 5, nc = ci & 31;                \
        cp16(smem_u32(&Bs[b][kk][nc * 4]),                                     \
             &g_W2r[(size_t)((kt) * 16 + kk) * 256 + colBase + nc * 4], 16);   \
    }                                                                          \
    cp_commit(); } while (0)
#define COMPUTE(b) do {                                                        \
    _Pragma("unroll")                                                          \
    for (int c8 = 0; c8 < 2; c8++) {                                           \
        int kk0 = c8 * 8;                                                      \
        uint32_t af[2][4], bf[8][2];                                           \
        _Pragma("unroll")                                                      \
        for (int mt = 0; mt < 2; mt++) {                                       \
            int r0 = wm + mt * 16 + grp;                                       \
            af[mt][0] = __float_as_uint(As[b][r0][kk0 + qp]);                  \
            af[mt][1] = __float_as_uint(As[b][r0 + 8][kk0 + qp]);              \
            af[mt][2] = __float_as_uint(As[b][r0][kk0 + qp + 4]);              \
            af[mt][3] = __float_as_uint(As[b][r0 + 8][kk0 + qp + 4]);          \
        }                                                                      \
        _Pragma("unroll")                                                      \
        for (int nt = 0; nt < 8; nt++) {                                       \
            int c0 = wn + nt * 8 + grp;                                        \
            bf[nt][0] = __float_as_uint(Bs[b][kk0 + qp][c0]);                  \
            bf[nt][1] = __float_as_uint(Bs[b][kk0 + qp + 4][c0]);              \
        }                                                                      \
        _Pragma("unroll")                                                      \
        for (int mt = 0; mt < 2; mt++)                                         \
            _Pragma("unroll")                                                  \
            for (int nt = 0; nt < 8; nt++)                                     \
                mma_tf32(acc[mt][nt], af[mt][0], af[mt][1], af[mt][2], af[mt][3], \
                         bf[nt][0], bf[nt][1]);                                \
    } } while (0)

    for (int cb = 0; cb < 2; cb++) {
        const int colBase = cb * 128;
        float acc[2][8][4];
#pragma unroll
        for (int mt = 0; mt < 2; mt++)
#pragma unroll
            for (int nt = 0; nt < 8; nt++)
#pragma unroll
                for (int r = 0; r < 4; r++) acc[mt][nt][r] = 0.f;

        LOAD_B(0, 0);
        LOAD_B(1, 1);
        LOAD_A(0); STS_A(0, 0); LOAD_A(1);
        cp_wait<1>(); __syncthreads();
        for (int kt = 0; kt < 16; kt++) {
            int b = kt & 1;
            if (kt + 1 < 16) STS_A(b ^ 1, kt + 1);
            if (kt + 2 < 16) LOAD_A(kt + 2);
            COMPUTE(b);
            if (kt + 1 < 16) cp_wait<0>();
            __syncthreads();
            if (kt + 2 < 16) LOAD_B(kt + 2, b);
        }

#pragma unroll
        for (int mt = 0; mt < 2; mt++) {
#pragma unroll
            for (int nt = 0; nt < 8; nt++) {
                int col = colBase + wn + nt * 8 + qp * 2;
                float b0 = b2[col], b1 = b2[col + 1];
                int gr0 = rowBase + wm + mt * 16 + grp;
                if (gr0 < n) {
                    float2 xr = *(const float2*)&x[(size_t)gr0 * CH + col];
                    *(float2*)&out[(size_t)gr0 * CH + col] =
                        make_float2(acc[mt][nt][0] + b0 + xr.x, acc[mt][nt][1] + b1 + xr.y);
                }
                int gr1 = gr0 + 8;
                if (gr1 < n) {
                    float2 xr = *(const float2*)&x[(size_t)gr1 * CH + col];
                    *(float2*)&out[(size_t)gr1 * CH + col] =
                        make_float2(acc[mt][nt][2] + b0 + xr.x, acc[mt][nt][3] + b1 + xr.y);
                }
            }
        }
        __syncthreads();            // protect As/Bs before next col-half
    }
#undef LOAD_A
#undef STS_A
#undef LOAD_B
#undef COMPUTE
}

// ---------------------------------------------------------------------------
extern "C" void kernel_launch(void* const* d_in, const int* in_sizes, int n_in,
                              void* d_out, int out_size) {
    const float* x     = (const float*)d_in[0];
    const float* Wl    = (const float*)d_in[1];
    const float* bl    = (const float*)d_in[2];
    const float* Wc    = (const float*)d_in[3];
    const float* gamma = (const float*)d_in[4];
    const float* beta  = (const float*)d_in[5];
    const float* W2    = (const float*)d_in[6];
    const float* b2    = (const float*)d_in[7];
    const int* in_idx  = (const int*)d_in[8];
    const int* out_idx = (const int*)d_in[9];
    float* out = (float*)d_out;

    int n = in_sizes[0] / CH;                 // 200000
    int M = in_sizes[8] / NPK;                // max pairs per (p,k)

    void* pS = nullptr; void* pQ = nullptr;
    cudaGetSymbolAddress(&pS, g_sum);
    cudaGetSymbolAddress(&pQ, g_sumsq);
    cudaMemsetAsync(pS, 0, CH * sizeof(float));
    cudaMemsetAsync(pQ, 0, CH * sizeof(float));

    prep_weights<<<2240, 256>>>(Wl, W2, Wc);
    count_pairs<<<1, 128>>>(in_idx, n, M);
    gemm_h<<<(n + 127) / 128, 256>>>(x, bl, n);
    conv_center<<<dim3((n + 127) / 128, PATHS), 256>>>(n);
    conv_scatter<<<dim3((M + 127) / 128, KOFF - 1, PATHS), 256>>>(in_idx, out_idx, M);
    bn_stats<<<2960, 256>>>(n);
    bn_finalize<<<1, 256>>>(gamma, beta, n);
    gemm_out<<<(n + 127) / 128, 256>>>(b2, x, out, n);
}

// round 9
// speedup vs baseline: 1.8231x; 1.0485x over previous
#include <cuda_runtime.h>
#include <cstdint>

#define CH 256
#define NMAX 200000
#define KOFF 27
#define PATHS 4
#define NPK (KOFF * PATHS)
#define GH_SMEM 81920   // As/Bs (37888) ∪ 2x Hstage (65536), + Ws (16384)

// Scratch (device globals: no allocation allowed in kernel_launch)
__device__ float g_H[(size_t)NMAX * CH];     // lifted features, pre-rounded tf32
__device__ float g_A[(size_t)NMAX * CH];     // conv result (fp32)
__device__ float g_sum[CH];
__device__ float g_sumsq[CH];
__device__ float g_scale[CH];
__device__ float g_shift[CH];
__device__ float g_Wlr[65536];               // Wl permuted to [k][n], tf32-rounded
__device__ float g_W2r[65536];               // W2 [k][n], tf32-rounded
__device__ float g_Wcr[442368];              // Wc tf32-rounded
__device__ int   g_cnt[NPK];                 // valid pair count per (p,k)

// ---------------------------------------------------------------------------
__device__ __forceinline__ float to_tf32(float f) {
    uint32_t u;
    asm("cvt.rna.tf32.f32 %0, %1;" : "=r"(u) : "f"(f));
    return __uint_as_float(u);
}

__device__ __forceinline__ void mma_tf32(float c[4], uint32_t a0, uint32_t a1,
                                         uint32_t a2, uint32_t a3,
                                         uint32_t b0, uint32_t b1) {
    asm volatile(
        "mma.sync.aligned.m16n8k8.row.col.f32.tf32.tf32.f32 "
        "{%0,%1,%2,%3}, {%4,%5,%6,%7}, {%8,%9}, {%0,%1,%2,%3};\n"
        : "+f"(c[0]), "+f"(c[1]), "+f"(c[2]), "+f"(c[3])
        : "r"(a0), "r"(a1), "r"(a2), "r"(a3), "r"(b0), "r"(b1));
}

__device__ __forceinline__ uint32_t smem_u32(const void* p) {
    return (uint32_t)__cvta_generic_to_shared(p);
}
__device__ __forceinline__ void cp16(uint32_t dst, const void* src, int sz) {
    asm volatile("cp.async.cg.shared.global [%0], [%1], 16, %2;"
                 :: "r"(dst), "l"(src), "r"(sz));
}
__device__ __forceinline__ void cp_commit() { asm volatile("cp.async.commit_group;"); }
template <int N> __device__ __forceinline__ void cp_wait() {
    asm volatile("cp.async.wait_group %0;" :: "n"(N));
}
__device__ __forceinline__ void red_v4(float* dst, float4 v) {
    asm volatile("red.global.add.v4.f32 [%0], {%1,%2,%3,%4};"
                 :: "l"(dst), "f"(v.x), "f"(v.y), "f"(v.z), "f"(v.w) : "memory");
}

// ---------------------------------------------------------------------------
__global__ void prep_weights(const float* __restrict__ Wl,
                             const float* __restrict__ W2,
                             const float* __restrict__ Wc) {
    int i = blockIdx.x * 256 + threadIdx.x;
    if (i < 65536) {
        int p = i >> 14, k = (i >> 6) & 255, d = i & 63;
        g_Wlr[k * 256 + p * 64 + d] = to_tf32(Wl[i]);
    } else if (i < 131072) {
        int j = i - 65536;
        g_W2r[j] = to_tf32(W2[j]);
    } else if (i < 131072 + 442368) {
        int j = i - 131072;
        g_Wcr[j] = to_tf32(Wc[j]);
    }
}

// Valid pairs per (p,k) are a prefix -> binary search the boundary.
__global__ void count_pairs(const int* __restrict__ in_idx, int n, int M) {
    int pk = threadIdx.x;
    if (pk >= NPK) return;
    const int* a = in_idx + (size_t)pk * M;
    int lo = 0, hi = M;
    while (lo < hi) {
        int mid = (lo + hi) >> 1;
        if (__ldg(&a[mid]) < n) lo = mid + 1; else hi = mid;
    }
    g_cnt[pk] = lo;
}

// ---------------------------------------------------------------------------
// H = tf32round(x @ Wl_cat + bl), tile 128x128 (grid (2, rows)), PLUS the
// fused center-offset conv: the H tile is staged to SMEM and multiplied by
// Wc[p][13] (two 128x64x64 passes), writing g_A directly.  Replaces the
// separate conv_center kernel (saves a full re-read of H from DRAM).
__global__ __launch_bounds__(256) void gemm_h(const float* __restrict__ x,
                                              const float* __restrict__ bl, int n) {
    extern __shared__ char dyn[];
    float (*As)[128][20] = (float (*)[128][20])(dyn);          // [2][128][20]
    float (*Bs)[16][136] = (float (*)[16][136])(dyn + 20480);  // [2][16][136]
    float* Wsc = (float*)(dyn + 65536);                        // [64*64] center W
    const int colBase = blockIdx.x * 128;
    const int rowBase = blockIdx.y * 128;
    const int tid = threadIdx.x;
    const int warpId = tid >> 5, lane = tid & 31;
    const int grp = lane >> 2, qp = lane & 3;
    const int wm = (warpId & 3) * 32, wn = (warpId >> 2) * 64;

    float acc[2][8][4];
#pragma unroll
    for (int mt = 0; mt < 2; mt++)
#pragma unroll
        for (int nt = 0; nt < 8; nt++)
#pragma unroll
            for (int r = 0; r < 4; r++) acc[mt][nt][r] = 0.f;

    float4 ar[2];
    int arow[2], akq[2];
#pragma unroll
    for (int i = 0; i < 2; i++) { int ci = tid + i * 256; arow[i] = ci >> 2; akq[i] = ci & 3; }

#define LOAD_A(kt) do {                                                        \
    _Pragma("unroll")                                                          \
    for (int i = 0; i < 2; i++) {                                              \
        int gr = rowBase + arow[i];                                            \
        ar[i] = (gr < n) ? *(const float4*)&x[(size_t)gr * CH + (kt) * 16 + akq[i] * 4] \
                         : make_float4(0.f, 0.f, 0.f, 0.f);                    \
    } } while (0)
#define STS_A(b) do {                                                          \
    _Pragma("unroll")                                                          \
    for (int i = 0; i < 2; i++) {                                              \
        float4 v = ar[i];                                                      \
        v.x = to_tf32(v.x); v.y = to_tf32(v.y); v.z = to_tf32(v.z); v.w = to_tf32(v.w); \
        *(float4*)&As[b][arow[i]][akq[i] * 4] = v;                             \
    } } while (0)
#define LOAD_B(kt, b) do {                                                     \
    _Pragma("unroll")                                                          \
    for (int i = 0; i < 2; i++) {                                              \
        int ci = tid + i * 256; int kk = ci >> 5, nc = ci & 31;                \
        cp16(smem_u32(&Bs[b][kk][nc * 4]),                                     \
             &g_Wlr[(size_t)((kt) * 16 + kk) * 256 + colBase + nc * 4], 16);   \
    }                                                                          \
    cp_commit(); } while (0)
#define COMPUTE(b) do {                                                        \
    _Pragma("unroll")                                                          \
    for (int c8 = 0; c8 < 2; c8++) {                                           \
        int kk0 = c8 * 8;                                                      \
        uint32_t af[2][4], bf[8][2];                                           \
        _Pragma("unroll")                                                      \
        for (int mt = 0; mt < 2; mt++) {                                       \
            int r0 = wm + mt * 16 + grp;                                       \
            af[mt][0] = __float_as_uint(As[b][r0][kk0 + qp]);                  \
            af[mt][1] = __float_as_uint(As[b][r0 + 8][kk0 + qp]);              \
            af[mt][2] = __float_as_uint(As[b][r0][kk0 + qp + 4]);              \
            af[mt][3] = __float_as_uint(As[b][r0 + 8][kk0 + qp + 4]);          \
        }                                                                      \
        _Pragma("unroll")                                                      \
        for (int nt = 0; nt < 8; nt++) {                                       \
            int c0 = wn + nt * 8 + grp;                                        \
            bf[nt][0] = __float_as_uint(Bs[b][kk0 + qp][c0]);                  \
            bf[nt][1] = __float_as_uint(Bs[b][kk0 + qp + 4][c0]);              \
        }                                                                      \
        _Pragma("unroll")                                                      \
        for (int mt = 0; mt < 2; mt++)                                         \
            _Pragma("unroll")                                                  \
            for (int nt = 0; nt < 8; nt++)                                     \
                mma_tf32(acc[mt][nt], af[mt][0], af[mt][1], af[mt][2], af[mt][3], \
                         bf[nt][0], bf[nt][1]);                                \
    } } while (0)

    LOAD_B(0, 0);
    LOAD_B(1, 1);
    LOAD_A(0); STS_A(0); LOAD_A(1);
    cp_wait<1>(); __syncthreads();
    for (int kt = 0; kt < 16; kt++) {
        int b = kt & 1;
        if (kt + 1 < 16) STS_A(b ^ 1);
        if (kt + 2 < 16) LOAD_A(kt + 2);
        COMPUTE(b);
        if (kt + 1 < 16) cp_wait<0>();
        __syncthreads();
        if (kt + 2 < 16) LOAD_B(kt + 2, b);
    }
#undef LOAD_A
#undef STS_A
#undef LOAD_B
#undef COMPUTE

    // Epilogue: write g_H and stage rounded H tile into two [128][64]
    // swizzled SMEM buffers (reusing the dead As/Bs region).
#pragma unroll
    for (int mt = 0; mt < 2; mt++) {
#pragma unroll
        for (int nt = 0; nt < 8; nt++) {
            int colL = wn + nt * 8 + qp * 2;       // 0..127 within tile
            int col = colBase + colL;
            float b0 = bl[col], b1 = bl[col + 1];
            float* H = (float*)(dyn + (colL >> 6) * 32768);
            int cl = colL & 63;
            int r0l = wm + mt * 16 + grp;
            int gr0 = rowBase + r0l;
            float2 o0 = make_float2(to_tf32(acc[mt][nt][0] + b0),
                                    to_tf32(acc[mt][nt][1] + b1));
            *(float2*)&H[r0l * 64 + (cl ^ ((r0l & 7) << 2))] = o0;
            if (gr0 < n) *(float2*)&g_H[(size_t)gr0 * CH + col] = o0;
            int r1l = r0l + 8, gr1 = gr0 + 8;
            float2 o1 = make_float2(to_tf32(acc[mt][nt][2] + b0),
                                    to_tf32(acc[mt][nt][3] + b1));
            *(float2*)&H[r1l * 64 + (cl ^ ((r1l & 7) << 2))] = o1;
            if (gr1 < n) *(float2*)&g_H[(size_t)gr1 * CH + col] = o1;
        }
    }
    __syncthreads();

    // Fused center conv: two 128x64x64 passes (one per path in this tile).
    // Warp grid: 4 row-groups x 2 col-groups; each warp covers 32 rows x 32
    // cols (nt = 0..3) -- full 128x64 tile.
    const int wmc = (warpId & 3) * 32, wnc = (warpId >> 2) * 32;
    const int sx = grp << 2, wsx = qp << 3;
    for (int pi = 0; pi < 2; pi++) {
        int pg = (colBase >> 6) + pi;             // global path index
        const float* Wpk = g_Wcr + ((size_t)pg * KOFF + 13) * 4096;
#pragma unroll
        for (int i = 0; i < 4; i++) {
            int ci = tid + i * 256;
            int c = ci >> 4, q = ci & 15;
            cp16(smem_u32(&Wsc[c * 64 + ((q * 4) ^ ((c & 3) << 3))]),
                 &Wpk[c * 64 + q * 4], 16);
        }
        cp_commit(); cp_wait<0>(); __syncthreads();

        float* H = (float*)(dyn + pi * 32768);
        float a2[2][4][4];
#pragma unroll
        for (int mt = 0; mt < 2; mt++)
#pragma unroll
            for (int nt = 0; nt < 4; nt++)
#pragma unroll
                for (int r = 0; r < 4; r++) a2[mt][nt][r] = 0.f;
#pragma unroll
        for (int c8 = 0; c8 < 8; c8++) {
            int kk0 = c8 * 8;
#pragma unroll
            for (int mt = 0; mt < 2; mt++) {
                int ra = wmc + mt * 16 + grp;
                uint32_t f0 = __float_as_uint(H[ra * 64 + ((kk0 + qp) ^ sx)]);
                uint32_t f1 = __float_as_uint(H[(ra + 8) * 64 + ((kk0 + qp) ^ sx)]);
                uint32_t f2 = __float_as_uint(H[ra * 64 + ((kk0 + qp + 4) ^ sx)]);
                uint32_t f3 = __float_as_uint(H[(ra + 8) * 64 + ((kk0 + qp + 4) ^ sx)]);
#pragma unroll
                for (int nt = 0; nt < 4; nt++) {
                    int c0 = wnc + nt * 8 + grp;
                    uint32_t b0 = __float_as_uint(Wsc[(kk0 + qp) * 64 + (c0 ^ wsx)]);
                    uint32_t b1 = __float_as_uint(Wsc[(kk0 + qp + 4) * 64 + (c0 ^ wsx)]);
                    mma_tf32(a2[mt][nt], f0, f1, f2, f3, b0, b1);
                }
            }
        }
        __syncthreads();                           // all mma reads of H done
#pragma unroll
        for (int mt = 0; mt < 2; mt++)
#pragma unroll
            for (int nt = 0; nt < 4; nt++) {
                int coll = wnc + nt * 8 + qp * 2;
                int rw = wmc + mt * 16 + grp;
                *(float2*)&H[rw * 64 + (coll ^ ((rw & 7) << 2))] =
                    make_float2(a2[mt][nt][0], a2[mt][nt][1]);
                int rw2 = rw + 8;
                *(float2*)&H[rw2 * 64 + (coll ^ ((rw2 & 7) << 2))] =
                    make_float2(a2[mt][nt][2], a2[mt][nt][3]);
            }
        __syncthreads();
#pragma unroll
        for (int i = 0; i < 8; i++) {
            int idx = tid + i * 256;
            int row = idx >> 4, c4 = idx & 15;
            int gr = rowBase + row;
            if (gr < n) {
                float4 v = *(const float4*)&H[row * 64 + ((c4 * 4) ^ ((row & 7) << 2))];
                *(float4*)&g_A[(size_t)gr * CH + pg * 64 + c4 * 4] = v;
            }
        }
        __syncthreads();
    }
}

// ---------------------------------------------------------------------------
// Sparse conv over the 26 non-center offsets: 128-pair tile per block,
// cp.async gather (XOR-swizzled), tf32 mma, SMEM-staged v4-RED scatter.
__global__ __launch_bounds__(256) void conv_scatter(const int* __restrict__ in_idx,
                                                    const int* __restrict__ out_idx,
                                                    int M) {
    __shared__ float Gs[128][64];   // swizzled: (m,c) at col c ^ ((m&7)<<2)
    __shared__ float Ws[64][64];    // swizzled: (k,c) at col c ^ ((k&3)<<3)
    __shared__ int Os[128];
    const int p = blockIdx.z;
    const int ky = blockIdx.y;
    const int k = ky + (ky >= 13);  // skip center
    const int pk = p * KOFF + k;
    const int cnt = g_cnt[pk];
    const int base0 = blockIdx.x * 128;
    if (base0 >= cnt) return;
    int rem = cnt - base0; if (rem > 128) rem = 128;
    const size_t base = (size_t)pk * M + base0;
    const int tid = threadIdx.x;

    const float* Wpk = g_Wcr + (size_t)pk * 4096;
#pragma unroll
    for (int i = 0; i < 4; i++) {
        int ci = tid + i * 256;
        int c = ci >> 4, q = ci & 15;
        cp16(smem_u32(&Ws[c][(q * 4) ^ ((c & 3) << 3)]), &Wpk[c * 64 + q * 4], 16);
    }
    {
        int m = tid >> 1, half = tid & 1;
        int jm = (m < rem) ? __ldg(&in_idx[base + m]) : 0;
        int sz = (m < rem) ? 16 : 0;
        const float* hp = &g_H[(size_t)jm * CH + p * 64 + half * 32];
#pragma unroll
        for (int q = 0; q < 8; q++) {
            int cb = half * 32 + q * 4;
            cp16(smem_u32(&Gs[m][cb ^ ((m & 7) << 2)]), hp + q * 4, sz);
        }
        if (half == 0)
            Os[m] = (m < rem) ? __ldg(&out_idx[base + m]) : -1;
    }
    cp_commit(); cp_wait<0>(); __syncthreads();

    const int warpId = tid >> 5, lane = tid & 31;
    const int grp = lane >> 2, qp = lane & 3;
    const int wm = (warpId & 3) * 32, wn = (warpId >> 2) * 32;
    const int sx = grp << 2, wsx = qp << 3;

    float acc[2][4][4];
#pragma unroll
    for (int mt = 0; mt < 2; mt++)
#pragma unroll
        for (int nt = 0; nt < 4; nt++)
#pragma unroll
            for (int r = 0; r < 4; r++) acc[mt][nt][r] = 0.f;

#pragma unroll
    for (int c8 = 0; c8 < 8; c8++) {
        int kk0 = c8 * 8;
        uint32_t af[2][4], bf[4][2];
#pragma unroll
        for (int mt = 0; mt < 2; mt++) {
            int r0 = wm + mt * 16 + grp;
            af[mt][0] = __float_as_uint(Gs[r0][(kk0 + qp) ^ sx]);
            af[mt][1] = __float_as_uint(Gs[r0 + 8][(kk0 + qp) ^ sx]);
            af[mt][2] = __float_as_uint(Gs[r0][(kk0 + qp + 4) ^ sx]);
            af[mt][3] = __float_as_uint(Gs[r0 + 8][(kk0 + qp + 4) ^ sx]);
        }
#pragma unroll
        for (int nt = 0; nt < 4; nt++) {
            int c0 = wn + nt * 8 + grp;
            bf[nt][0] = __float_as_uint(Ws[kk0 + qp][c0 ^ wsx]);
            bf[nt][1] = __float_as_uint(Ws[kk0 + qp + 4][c0 ^ wsx]);
        }
#pragma unroll
        for (int mt = 0; mt < 2; mt++)
#pragma unroll
            for (int nt = 0; nt < 4; nt++)
                mma_tf32(acc[mt][nt], af[mt][0], af[mt][1], af[mt][2], af[mt][3],
                         bf[nt][0], bf[nt][1]);
    }
    __syncthreads();

#pragma unroll
    for (int mt = 0; mt < 2; mt++)
#pragma unroll
        for (int nt = 0; nt < 4; nt++) {
            int col = wn + nt * 8 + qp * 2;
            int r0 = wm + mt * 16 + grp;
            *(float2*)&Gs[r0][col ^ ((r0 & 7) << 2)] =
                make_float2(acc[mt][nt][0], acc[mt][nt][1]);
            *(float2*)&Gs[r0 + 8][col ^ ((r0 & 7) << 2)] =
                make_float2(acc[mt][nt][2], acc[mt][nt][3]);
        }
    __syncthreads();

#pragma unroll
    for (int i = 0; i < 8; i++) {
        int idx = tid + i * 256;
        int row = idx >> 4, c4 = idx & 15;
        int o = Os[row];
        if (o >= 0) {
            float4 v = *(const float4*)&Gs[row][(c4 * 4) ^ ((row & 7) << 2)];
            red_v4(&g_A[(size_t)o * CH + p * 64 + c4 * 4], v);
        }
    }
}

// ---------------------------------------------------------------------------
__global__ __launch_bounds__(256) void bn_stats(int n) {
    __shared__ float4 rs[4][64], rq[4][64];
    int tid = threadIdx.x;
    int cq = tid & 63;
    int rl = tid >> 6;
    float4 s = make_float4(0.f, 0.f, 0.f, 0.f);
    float4 s2 = make_float4(0.f, 0.f, 0.f, 0.f);
#pragma unroll 8
    for (int r = blockIdx.x * 4 + rl; r < n; r += gridDim.x * 4) {
        float4 v = *(const float4*)&g_A[(size_t)r * CH + cq * 4];
        s.x += v.x; s.y += v.y; s.z += v.z; s.w += v.w;
        s2.x += v.x * v.x; s2.y += v.y * v.y; s2.z += v.z * v.z; s2.w += v.w * v.w;
    }
    rs[rl][cq] = s; rq[rl][cq] = s2;
    __syncthreads();
    if (rl == 0) {
#pragma unroll
        for (int i = 1; i < 4; i++) {
            float4 a = rs[i][cq], b = rq[i][cq];
            s.x += a.x; s.y += a.y; s.z += a.z; s.w += a.w;
            s2.x += b.x; s2.y += b.y; s2.z += b.z; s2.w += b.w;
        }
        int c = cq * 4;
        atomicAdd(&g_sum[c + 0], s.x);  atomicAdd(&g_sum[c + 1], s.y);
        atomicAdd(&g_sum[c + 2], s.z);  atomicAdd(&g_sum[c + 3], s.w);
        atomicAdd(&g_sumsq[c + 0], s2.x); atomicAdd(&g_sumsq[c + 1], s2.y);
        atomicAdd(&g_sumsq[c + 2], s2.z); atomicAdd(&g_sumsq[c + 3], s2.w);
    }
}

__global__ void bn_finalize(const float* __restrict__ gamma,
                            const float* __restrict__ beta, int n) {
    int j = threadIdx.x;
    float inv = 1.f / (float)n;
    float mu = g_sum[j] * inv;
    float var = g_sumsq[j] * inv - mu * mu;
    float sc = gamma[j] * rsqrtf(var + 1e-5f);
    g_scale[j] = sc;
    g_shift[j] = beta[j] - mu * sc;
}

// ---------------------------------------------------------------------------
// out = relu(bn(A)) @ W2 + b2 + x.  R5 form: grid (2, rows), 2-stage pipeline.
__global__ __launch_bounds__(256) void gemm_out(const float* __restrict__ b2,
                                                const float* __restrict__ x,
                                                float* __restrict__ out, int n) {
    __shared__ float As[2][128][20];
    __shared__ float Bs[2][16][136];
    __shared__ float sc[256], sh[256];
    const int colBase = blockIdx.x * 128;
    const int rowBase = blockIdx.y * 128;
    const int tid = threadIdx.x;
    const int warpId = tid >> 5, lane = tid & 31;
    const int grp = lane >> 2, qp = lane & 3;
    const int wm = (warpId & 3) * 32, wn = (warpId >> 2) * 64;

    sc[tid] = g_scale[tid];
    sh[tid] = g_shift[tid];

    float acc[2][8][4];
#pragma unroll
    for (int mt = 0; mt < 2; mt++)
#pragma unroll
        for (int nt = 0; nt < 8; nt++)
#pragma unroll
            for (int r = 0; r < 4; r++) acc[mt][nt][r] = 0.f;

    float4 ar[2];
    int arow[2], akq[2];
#pragma unroll
    for (int i = 0; i < 2; i++) { int ci = tid + i * 256; arow[i] = ci >> 2; akq[i] = ci & 3; }

#define LOAD_A(kt) do {                                                        \
    _Pragma("unroll")                                                          \
    for (int i = 0; i < 2; i++) {                                              \
        int gr = rowBase + arow[i];                                            \
        ar[i] = (gr < n) ? *(const float4*)&g_A[(size_t)gr * CH + (kt) * 16 + akq[i] * 4] \
                         : make_float4(0.f, 0.f, 0.f, 0.f);                    \
    } } while (0)
#define STS_A(b, kt) do {                                                      \
    _Pragma("unroll")                                                          \
    for (int i = 0; i < 2; i++) {                                              \
        float4 v = ar[i];                                                      \
        int c0 = (kt) * 16 + akq[i] * 4;                                       \
        v.x = to_tf32(fmaxf(v.x * sc[c0 + 0] + sh[c0 + 0], 0.f));              \
        v.y = to_tf32(fmaxf(v.y * sc[c0 + 1] + sh[c0 + 1], 0.f));              \
        v.z = to_tf32(fmaxf(v.z * sc[c0 + 2] + sh[c0 + 2], 0.f));              \
        v.w = to_tf32(fmaxf(v.w * sc[c0 + 3] + sh[c0 + 3], 0.f));              \
        *(float4*)&As[b][arow[i]][akq[i] * 4] = v;                             \
    } } while (0)
#define LOAD_B(kt, b) do {                                                     \
    _Pragma("unroll")                                                          \
    for (int i = 0; i < 2; i++) {                                              \
        int ci = tid + i * 256; int kk = ci >> 5, nc = ci & 31;                \
        cp16(smem_u32(&Bs[b][kk][nc * 4]),                                     \
             &g_W2r[(size_t)((kt) * 16 + kk) * 256 + colBase + nc * 4], 16);   \
    }                                                                          \
    cp_commit(); } while (0)
#define COMPUTE(b) do {                                                        \
    _Pragma("unroll")                                                          \
    for (int c8 = 0; c8 < 2; c8++) {                                           \
        int kk0 = c8 * 8;                                                      \
        uint32_t af[2][4], bf[8][2];                                           \
        _Pragma("unroll")                                                      \
        for (int mt = 0; mt < 2; mt++) {                                       \
            int r0 = wm + mt * 16 + grp;                                       \
            af[mt][0] = __float_as_uint(As[b][r0][kk0 + qp]);                  \
            af[mt][1] = __float_as_uint(As[b][r0 + 8][kk0 + qp]);              \
            af[mt][2] = __float_as_uint(As[b][r0][kk0 + qp + 4]);              \
            af[mt][3] = __float_as_uint(As[b][r0 + 8][kk0 + qp + 4]);          \
        }                                                                      \
        _Pragma("unroll")                                                      \
        for (int nt = 0; nt < 8; nt++) {                                       \
            int c0 = wn + nt * 8 + grp;                                        \
            bf[nt][0] = __float_as_uint(Bs[b][kk0 + qp][c0]);                  \
            bf[nt][1] = __float_as_uint(Bs[b][kk0 + qp + 4][c0]);              \
        }                                                                      \
        _Pragma("unroll")                                                      \
        for (int mt = 0; mt < 2; mt++)                                         \
            _Pragma("unroll")                                                  \
            for (int nt = 0; nt < 8; nt++)                                     \
                mma_tf32(acc[mt][nt], af[mt][0], af[mt][1], af[mt][2], af[mt][3], \
                         bf[nt][0], bf[nt][1]);                                \
    } } while (0)

    LOAD_B(0, 0);
    LOAD_B(1, 1);
    LOAD_A(0);
    __syncthreads();                 // publish sc/sh before STS_A uses them
    STS_A(0, 0); LOAD_A(1);
    cp_wait<1>(); __syncthreads();
    for (int kt = 0; kt < 16; kt++) {
        int b = kt & 1;
        if (kt + 1 < 16) STS_A(b ^ 1, kt + 1);
        if (kt + 2 < 16) LOAD_A(kt + 2);
        COMPUTE(b);
        if (kt + 1 < 16) cp_wait<0>();
        __syncthreads();
        if (kt + 2 < 16) LOAD_B(kt + 2, b);
    }
#undef LOAD_A
#undef STS_A
#undef LOAD_B
#undef COMPUTE

#pragma unroll
    for (int mt = 0; mt < 2; mt++) {
#pragma unroll
        for (int nt = 0; nt < 8; nt++) {
            int col = colBase + wn + nt * 8 + qp * 2;
            float b0 = b2[col], b1 = b2[col + 1];
            int gr0 = rowBase + wm + mt * 16 + grp;
            if (gr0 < n) {
                float2 xr = *(const float2*)&x[(size_t)gr0 * CH + col];
                *(float2*)&out[(size_t)gr0 * CH + col] =
                    make_float2(acc[mt][nt][0] + b0 + xr.x, acc[mt][nt][1] + b1 + xr.y);
            }
            int gr1 = gr0 + 8;
            if (gr1 < n) {
                float2 xr = *(const float2*)&x[(size_t)gr1 * CH + col];
                *(float2*)&out[(size_t)gr1 * CH + col] =
                    make_float2(acc[mt][nt][2] + b0 + xr.x, acc[mt][nt][3] + b1 + xr.y);
            }
        }
    }
}

// ---------------------------------------------------------------------------
extern "C" void kernel_launch(void* const* d_in, const int* in_sizes, int n_in,
                              void* d_out, int out_size) {
    const float* x     = (const float*)d_in[0];
    const float* Wl    = (const float*)d_in[1];
    const float* bl    = (const float*)d_in[2];
    const float* Wc    = (const float*)d_in[3];
    const float* gamma = (const float*)d_in[4];
    const float* beta  = (const float*)d_in[5];
    const float* W2    = (const float*)d_in[6];
    const float* b2    = (const float*)d_in[7];
    const int* in_idx  = (const int*)d_in[8];
    const int* out_idx = (const int*)d_in[9];
    float* out = (float*)d_out;

    int n = in_sizes[0] / CH;                 // 200000
    int M = in_sizes[8] / NPK;                // max pairs per (p,k)

    cudaFuncSetAttribute(gemm_h, cudaFuncAttributeMaxDynamicSharedMemorySize,
                         GH_SMEM);

    void* pS = nullptr; void* pQ = nullptr;
    cudaGetSymbolAddress(&pS, g_sum);
    cudaGetSymbolAddress(&pQ, g_sumsq);
    cudaMemsetAsync(pS, 0, CH * sizeof(float));
    cudaMemsetAsync(pQ, 0, CH * sizeof(float));

    prep_weights<<<2240, 256>>>(Wl, W2, Wc);
    count_pairs<<<1, 128>>>(in_idx, n, M);
    gemm_h<<<dim3(2, (n + 127) / 128), 256, GH_SMEM>>>(x, bl, n);
    conv_scatter<<<dim3((M + 127) / 128, KOFF - 1, PATHS), 256>>>(in_idx, out_idx, M);
    bn_stats<<<2960, 256>>>(n);
    bn_finalize<<<1, 256>>>(gamma, beta, n);
    gemm_out<<<dim3(2, (n + 127) / 128), 256>>>(b2, x, out, n);
}